// round 1
// baseline (speedup 1.0000x reference)
#include <cuda_runtime.h>

#define TOK 512
#define HID 2048
#define NE  64
#define NI  768
#define TOPK 8
#define CAP 256
#define KB  16

// ---------------- scratch (static device allocations; no cudaMalloc) -------
__device__ int   g_counts[NE];
__device__ int   g_sel[TOK * TOPK];
__device__ float g_rw[TOK * TOPK];
__device__ int   g_eslot[TOK * TOPK];          // e*CAP+slot or -1
__device__ int   g_toklist[NE * CAP];
__device__ float g_hbuf[(size_t)NE * CAP * NI];   // SwiGLU intermediate
__device__ float g_ybuf[(size_t)NE * CAP * HID];  // per-assignment expert output

// ---------------- router: logits, top-8, renormalized weights --------------
__global__ void router_kernel(const float* __restrict__ x,
                              const float* __restrict__ gw,
                              float* __restrict__ logits_out)
{
    int t = blockIdx.x;
    int e = threadIdx.x;            // 64 threads, one expert each
    __shared__ float sl[NE];

    const float4* xr = (const float4*)(x + (size_t)t * HID);
    const float4* gr = (const float4*)(gw + (size_t)e * HID);
    float acc = 0.f;
#pragma unroll 4
    for (int k = 0; k < HID / 4; k++) {
        float4 a = xr[k], b = gr[k];
        acc += a.x * b.x + a.y * b.y + a.z * b.z + a.w * b.w;
    }
    sl[e] = acc;
    if (logits_out) logits_out[t * NE + e] = acc;
    __syncthreads();

    if (e == 0) {
        float tmp[NE];
        for (int i = 0; i < NE; i++) tmp[i] = sl[i];
        int   sid[TOPK];
        float lv[TOPK];
        for (int kk = 0; kk < TOPK; kk++) {
            int bi = 0; float bv = -3.4e38f;
            for (int i = 0; i < NE; i++)
                if (tmp[i] > bv) { bv = tmp[i]; bi = i; }
            sid[kk] = bi; lv[kk] = bv; tmp[bi] = -3.4e38f;
        }
        // softmax denominator cancels under top-k renorm: softmax over top-8 logits
        float m = lv[0];
        float w[TOPK], s = 0.f;
        for (int kk = 0; kk < TOPK; kk++) { w[kk] = expf(lv[kk] - m); s += w[kk]; }
        float inv = 1.f / s;
        for (int kk = 0; kk < TOPK; kk++) {
            g_sel[t * TOPK + kk] = sid[kk];
            g_rw[t * TOPK + kk]  = w[kk] * inv;
        }
    }
}

// ---------------- dispatch: per-expert slot assignment ---------------------
__global__ void zero_counts_kernel()
{
    if (threadIdx.x < NE) g_counts[threadIdx.x] = 0;
}

__global__ void dispatch_kernel()
{
    int a = blockIdx.x * blockDim.x + threadIdx.x;
    if (a >= TOK * TOPK) return;
    int e = g_sel[a];
    int s = atomicAdd(&g_counts[e], 1);
    if (s < CAP) {
        g_toklist[e * CAP + s] = a >> 3;   // token id
        g_eslot[a] = e * CAP + s;
    } else {
        g_eslot[a] = -1;                   // dropped (matches reference valid-mask)
    }
}

// ---------------- GEMM1: g = X W1^T, u = X W3^T, h = silu(g)*u -------------
// tile: [64 tokens x 64 i], k over HID, 256 threads, 4x4 micro-tiles
__global__ __launch_bounds__(256) void gemm1_kernel(const float* __restrict__ x,
                                                    const float* __restrict__ w1,
                                                    const float* __restrict__ w3)
{
    int e  = blockIdx.x;
    int it = blockIdx.y;     // i-tile  (NI/64 = 12)
    int tt = blockIdx.z;     // token tile (CAP/64 = 4)
    int cnt = min(g_counts[e], CAP);
    int t0 = tt * 64;
    if (t0 >= cnt) return;
    int i0 = it * 64;

    __shared__ float xs[KB][65];
    __shared__ float as[KB][65];
    __shared__ float bs[KB][65];

    int tid = threadIdx.x;
    int tx = tid & 15, ty = tid >> 4;
    int fc = tid & 15;           // fill column (k within KB)
    int fr0 = tid >> 4;          // fill base row

    // hoist token ids for the 4 fill rows this thread touches
    int ftok[4];
#pragma unroll
    for (int n = 0; n < 4; n++) {
        int r = fr0 + n * 16;
        ftok[n] = (t0 + r < cnt) ? g_toklist[e * CAP + t0 + r] : -1;
    }

    float acc1[4][4] = {}, acc3[4][4] = {};

    for (int k0 = 0; k0 < HID; k0 += KB) {
#pragma unroll
        for (int n = 0; n < 4; n++) {
            int r = fr0 + n * 16;
            float xv = 0.f;
            if (ftok[n] >= 0) xv = x[(size_t)ftok[n] * HID + k0 + fc];
            xs[fc][r] = xv;
            as[fc][r] = w1[((size_t)e * NI + i0 + r) * HID + k0 + fc];
            bs[fc][r] = w3[((size_t)e * NI + i0 + r) * HID + k0 + fc];
        }
        __syncthreads();
#pragma unroll
        for (int k = 0; k < KB; k++) {
            float a[4], b1[4], b3[4];
#pragma unroll
            for (int i = 0; i < 4; i++) a[i] = xs[k][ty * 4 + i];
#pragma unroll
            for (int j = 0; j < 4; j++) { b1[j] = as[k][tx * 4 + j]; b3[j] = bs[k][tx * 4 + j]; }
#pragma unroll
            for (int i = 0; i < 4; i++)
#pragma unroll
                for (int j = 0; j < 4; j++) {
                    acc1[i][j] += a[i] * b1[j];
                    acc3[i][j] += a[i] * b3[j];
                }
        }
        __syncthreads();
    }

#pragma unroll
    for (int i = 0; i < 4; i++) {
        int r = t0 + ty * 4 + i;
        if (r >= cnt) continue;
#pragma unroll
        for (int j = 0; j < 4; j++) {
            float g = acc1[i][j], u = acc3[i][j];
            float hv = (g / (1.f + expf(-g))) * u;
            g_hbuf[((size_t)e * CAP + r) * NI + i0 + tx * 4 + j] = hv;
        }
    }
}

// ---------------- GEMM2: y = h W2^T ---------------------------------------
__global__ __launch_bounds__(256) void gemm2_kernel(const float* __restrict__ w2)
{
    int e  = blockIdx.x;
    int ht = blockIdx.y;     // h-dim tile (HID/64 = 32)
    int tt = blockIdx.z;
    int cnt = min(g_counts[e], CAP);
    int t0 = tt * 64;
    if (t0 >= cnt) return;
    int h0 = ht * 64;

    __shared__ float hs[KB][65];
    __shared__ float ws[KB][65];

    int tid = threadIdx.x;
    int tx = tid & 15, ty = tid >> 4;
    int fc = tid & 15;
    int fr0 = tid >> 4;

    float acc[4][4] = {};

    for (int k0 = 0; k0 < NI; k0 += KB) {
#pragma unroll
        for (int n = 0; n < 4; n++) {
            int r = fr0 + n * 16;
            float hv = 0.f;
            if (t0 + r < cnt) hv = g_hbuf[((size_t)e * CAP + t0 + r) * NI + k0 + fc];
            hs[fc][r] = hv;
            ws[fc][r] = w2[((size_t)e * HID + h0 + r) * NI + k0 + fc];
        }
        __syncthreads();
#pragma unroll
        for (int k = 0; k < KB; k++) {
            float a[4], b[4];
#pragma unroll
            for (int i = 0; i < 4; i++) a[i] = hs[k][ty * 4 + i];
#pragma unroll
            for (int j = 0; j < 4; j++) b[j] = ws[k][tx * 4 + j];
#pragma unroll
            for (int i = 0; i < 4; i++)
#pragma unroll
                for (int j = 0; j < 4; j++) acc[i][j] += a[i] * b[j];
        }
        __syncthreads();
    }

#pragma unroll
    for (int i = 0; i < 4; i++) {
        int r = t0 + ty * 4 + i;
        if (r >= cnt) continue;
#pragma unroll
        for (int j = 0; j < 4; j++)
            g_ybuf[((size_t)e * CAP + r) * HID + h0 + tx * 4 + j] = acc[i][j];
    }
}

// ---------------- combine: weighted gather back to tokens ------------------
__global__ void combine_kernel(float* __restrict__ out)
{
    int t = blockIdx.x;
    __shared__ int   es[TOPK];
    __shared__ float wk[TOPK];
    if (threadIdx.x < TOPK) {
        es[threadIdx.x] = g_eslot[t * TOPK + threadIdx.x];
        wk[threadIdx.x] = g_rw[t * TOPK + threadIdx.x];
    }
    __syncthreads();
    for (int h = threadIdx.x; h < HID; h += blockDim.x) {
        float acc = 0.f;
#pragma unroll
        for (int kk = 0; kk < TOPK; kk++) {
            int s = es[kk];
            if (s >= 0) acc += wk[kk] * g_ybuf[(size_t)s * HID + h];
        }
        out[(size_t)t * HID + h] = acc;
    }
}

// ---------------- launch ----------------------------------------------------
extern "C" void kernel_launch(void* const* d_in, const int* in_sizes, int n_in,
                              void* d_out, int out_size)
{
    const float* x  = (const float*)d_in[0];
    const float* gw = (const float*)d_in[1];
    const float* w1 = (const float*)d_in[2];
    const float* w2 = (const float*)d_in[3];
    const float* w3 = (const float*)d_in[4];
    float* out = (float*)d_out;
    float* logits = (out_size >= TOK * HID + TOK * NE) ? out + (size_t)TOK * HID
                                                       : nullptr;

    zero_counts_kernel<<<1, 64>>>();
    router_kernel<<<TOK, 64>>>(x, gw, logits);
    dispatch_kernel<<<(TOK * TOPK + 255) / 256, 256>>>();

    dim3 g1(NE, NI / 64, CAP / 64);
    gemm1_kernel<<<g1, 256>>>(x, w1, w3);

    dim3 g2(NE, HID / 64, CAP / 64);
    gemm2_kernel<<<g2, 256>>>(w2);

    combine_kernel<<<TOK, 256>>>(out);
}

// round 4
// speedup vs baseline: 2.1104x; 2.1104x over previous
#include <cuda_runtime.h>
#include <cuda_bf16.h>
#include <cstdint>

#define TOK 512
#define HID 2048
#define NE  64
#define NI  768
#define TOPK 8
#define CAP 256

#define ROWB  80u              // smem row stride bytes (32 bf16 = 64B + 16B pad)
#define TILEB (128u * ROWB)    // 10240 B per matrix tile
#define BUFB  (4u * TILEB)     // A_hi, A_lo, B_hi, B_lo = 40960 B per stage
#define SMEM_BYTES (2 * BUFB)  // 81920 B (double buffered)

// ---------------- scratch (static device allocations) ----------------------
__device__ int   g_counts[NE];
__device__ int   g_sel[TOK * TOPK];
__device__ float g_rw[TOK * TOPK];
__device__ int   g_eslot[TOK * TOPK];
__device__ int   g_toklist[NE * CAP];
__device__ float g_hbuf[(size_t)NE * CAP * NI];
__device__ float g_ybuf[(size_t)NE * CAP * HID];

// ---------------- helpers ---------------------------------------------------
__device__ __forceinline__ uint32_t smem_u32(const void* p) {
    uint32_t a;
    asm("{ .reg .u64 t; cvta.to.shared.u64 t, %1; cvt.u32.u64 %0, t; }"
        : "=r"(a) : "l"(p));
    return a;
}

__device__ __forceinline__ void ldsm4(uint32_t* r, uint32_t addr) {
    asm volatile("ldmatrix.sync.aligned.m8n8.x4.shared.b16 {%0,%1,%2,%3}, [%4];"
                 : "=r"(r[0]), "=r"(r[1]), "=r"(r[2]), "=r"(r[3]) : "r"(addr));
}

__device__ __forceinline__ void mma16816(float* d, const uint32_t* a,
                                         uint32_t b0, uint32_t b1) {
    asm volatile(
        "mma.sync.aligned.m16n8k16.row.col.f32.bf16.bf16.f32 "
        "{%0,%1,%2,%3}, {%4,%5,%6,%7}, {%8,%9}, {%0,%1,%2,%3};"
        : "+f"(d[0]), "+f"(d[1]), "+f"(d[2]), "+f"(d[3])
        : "r"(a[0]), "r"(a[1]), "r"(a[2]), "r"(a[3]), "r"(b0), "r"(b1));
}

// split fp32 -> bf16 hi + bf16 residual lo; store 8B each into hi/lo tiles
__device__ __forceinline__ void sts_split(uint32_t hi_a, uint32_t lo_a, float4 v) {
    __nv_bfloat16 hx = __float2bfloat16(v.x), hy = __float2bfloat16(v.y),
                  hz = __float2bfloat16(v.z), hw = __float2bfloat16(v.w);
    float lx = v.x - __bfloat162float(hx), ly = v.y - __bfloat162float(hy),
          lz = v.z - __bfloat162float(hz), lw = v.w - __bfloat162float(hw);
    uint32_t h01 = (uint32_t)__bfloat16_as_ushort(hx) | ((uint32_t)__bfloat16_as_ushort(hy) << 16);
    uint32_t h23 = (uint32_t)__bfloat16_as_ushort(hz) | ((uint32_t)__bfloat16_as_ushort(hw) << 16);
    __nv_bfloat16 kx = __float2bfloat16(lx), ky = __float2bfloat16(ly),
                  kz = __float2bfloat16(lz), kw = __float2bfloat16(lw);
    uint32_t l01 = (uint32_t)__bfloat16_as_ushort(kx) | ((uint32_t)__bfloat16_as_ushort(ky) << 16);
    uint32_t l23 = (uint32_t)__bfloat16_as_ushort(kz) | ((uint32_t)__bfloat16_as_ushort(kw) << 16);
    asm volatile("st.shared.v2.b32 [%0], {%1,%2};" :: "r"(hi_a), "r"(h01), "r"(h23) : "memory");
    asm volatile("st.shared.v2.b32 [%0], {%1,%2};" :: "r"(lo_a), "r"(l01), "r"(l23) : "memory");
}

// mma over one K=32 chunk. sb = stage base (A_hi | A_lo | B_hi | B_lo tiles).
__device__ __forceinline__ void compute_chunk(uint32_t sb, float acc[2][8][4],
                                              uint32_t aoff, uint32_t boff) {
#pragma unroll
    for (int ks = 0; ks < 2; ks++) {
        uint32_t ah[2][4], al[2][4];
#pragma unroll
        for (int mt = 0; mt < 2; mt++) {
            uint32_t ao = aoff + mt * (16 * ROWB) + ks * 32;
            ldsm4(ah[mt], sb + ao);
            ldsm4(al[mt], sb + TILEB + ao);
        }
#pragma unroll
        for (int ng = 0; ng < 4; ng++) {
            uint32_t bo = boff + ng * (16 * ROWB) + ks * 32;
            uint32_t bh[4], bl[4];
            ldsm4(bh, sb + 2 * TILEB + bo);
            ldsm4(bl, sb + 3 * TILEB + bo);
#pragma unroll
            for (int t = 0; t < 2; t++) {
#pragma unroll
                for (int mt = 0; mt < 2; mt++) {
                    float* d = acc[mt][ng * 2 + t];
                    mma16816(d, ah[mt], bh[t], bh[2 + t]);
                    mma16816(d, ah[mt], bl[t], bl[2 + t]);
                    mma16816(d, al[mt], bh[t], bh[2 + t]);
                }
            }
        }
    }
}

// ---------------- router (fp32 exact: feeds top-k) -------------------------
__global__ void router_kernel(const float* __restrict__ x,
                              const float* __restrict__ gw,
                              float* __restrict__ logits_out)
{
    int t = blockIdx.x;
    int e = threadIdx.x;
    __shared__ float sl[NE];
    const float4* xr = (const float4*)(x + (size_t)t * HID);
    const float4* gr = (const float4*)(gw + (size_t)e * HID);
    float acc = 0.f;
#pragma unroll 4
    for (int k = 0; k < HID / 4; k++) {
        float4 a = xr[k], b = gr[k];
        acc += a.x * b.x + a.y * b.y + a.z * b.z + a.w * b.w;
    }
    sl[e] = acc;
    if (logits_out) logits_out[t * NE + e] = acc;
    __syncthreads();
    if (e == 0) {
        float tmp[NE];
        for (int i = 0; i < NE; i++) tmp[i] = sl[i];
        int sid[TOPK]; float lv[TOPK];
        for (int kk = 0; kk < TOPK; kk++) {
            int bi = 0; float bv = -3.4e38f;
            for (int i = 0; i < NE; i++)
                if (tmp[i] > bv) { bv = tmp[i]; bi = i; }
            sid[kk] = bi; lv[kk] = bv; tmp[bi] = -3.4e38f;
        }
        float m = lv[0], w[TOPK], s = 0.f;
        for (int kk = 0; kk < TOPK; kk++) { w[kk] = expf(lv[kk] - m); s += w[kk]; }
        float inv = 1.f / s;
        for (int kk = 0; kk < TOPK; kk++) {
            g_sel[t * TOPK + kk] = sid[kk];
            g_rw[t * TOPK + kk] = w[kk] * inv;
        }
    }
}

__global__ void zero_counts_kernel() { if (threadIdx.x < NE) g_counts[threadIdx.x] = 0; }

__global__ void dispatch_kernel()
{
    int a = blockIdx.x * blockDim.x + threadIdx.x;
    if (a >= TOK * TOPK) return;
    int e = g_sel[a];
    int s = atomicAdd(&g_counts[e], 1);
    if (s < CAP) { g_toklist[e * CAP + s] = a >> 3; g_eslot[a] = e * CAP + s; }
    else g_eslot[a] = -1;
}

// ---------------- GEMM1: [128 tok x (64 g | 64 u)] per CTA, fused SwiGLU ---
__global__ __launch_bounds__(256) void gemm1_kernel(const float* __restrict__ x,
                                                    const float* __restrict__ w1,
                                                    const float* __restrict__ w3)
{
    int e = blockIdx.x, it = blockIdx.y, mtile = blockIdx.z;
    int cnt = min(g_counts[e], CAP);
    int m0 = mtile * 128;
    if (m0 >= cnt) return;
    int i0 = it * 64;

    extern __shared__ char smraw[];
    uint32_t sb0 = smem_u32(smraw);

    int tid = threadIdx.x, lane = tid & 31, wid = tid >> 5;
    int wr = wid & 3, wc = wid >> 2;
    int mr = wr * 32, nb = wc * 64;

    // fill mapping: 128x32 fp32 tile, 8 float4 per row, 4 row passes
    int r = tid >> 3, c4 = tid & 7;
    const float* apt[4]; const float* bpt[4];
    uint32_t soff[4];
#pragma unroll
    for (int p = 0; p < 4; p++) {
        int rp = r + 32 * p;
        int grw = m0 + rp;
        apt[p] = (grw < cnt) ? x + (size_t)g_toklist[e * CAP + grw] * HID + c4 * 4 : nullptr;
        bpt[p] = (p < 2) ? w1 + ((size_t)e * NI + i0 + rp) * HID + c4 * 4
                         : w3 + ((size_t)e * NI + i0 + rp - 64) * HID + c4 * 4;
        soff[p] = (uint32_t)(rp * ROWB + c4 * 8);
    }

    // ldmatrix lane addressing
    uint32_t rowpart = (lane & 7) + ((lane >> 3) & 1) * 8;
    uint32_t colp = (lane >> 4) & 1;
    uint32_t aoff = (uint32_t)((mr + rowpart) * ROWB + colp * 16);
    uint32_t boff = (uint32_t)((nb + rowpart) * ROWB + colp * 16);

    float acc[2][8][4];
#pragma unroll
    for (int mt = 0; mt < 2; mt++)
#pragma unroll
        for (int n = 0; n < 8; n++)
#pragma unroll
            for (int q = 0; q < 4; q++) acc[mt][n][q] = 0.f;

    float4 va[4], vb[4];
#pragma unroll
    for (int p = 0; p < 4; p++) {
        va[p] = apt[p] ? __ldg((const float4*)apt[p]) : make_float4(0, 0, 0, 0);
        vb[p] = __ldg((const float4*)bpt[p]);
    }
#pragma unroll
    for (int p = 0; p < 4; p++) {
        sts_split(sb0 + soff[p],             sb0 + TILEB + soff[p],     va[p]);
        sts_split(sb0 + 2 * TILEB + soff[p], sb0 + 3 * TILEB + soff[p], vb[p]);
    }
    __syncthreads();

    const int NCH = HID / 32;
    for (int ch = 0; ch < NCH; ch++) {
        uint32_t cur = sb0 + (uint32_t)(ch & 1) * BUFB;
        bool more = (ch + 1 < NCH);
        if (more) {
            int off = (ch + 1) * 32;
#pragma unroll
            for (int p = 0; p < 4; p++) {
                va[p] = apt[p] ? __ldg((const float4*)(apt[p] + off)) : make_float4(0, 0, 0, 0);
                vb[p] = __ldg((const float4*)(bpt[p] + off));
            }
        }
        compute_chunk(cur, acc, aoff, boff);
        if (more) {
            uint32_t nxt = sb0 + (uint32_t)((ch + 1) & 1) * BUFB;
#pragma unroll
            for (int p = 0; p < 4; p++) {
                sts_split(nxt + soff[p],             nxt + TILEB + soff[p],     va[p]);
                sts_split(nxt + 2 * TILEB + soff[p], nxt + 3 * TILEB + soff[p], vb[p]);
            }
        }
        __syncthreads();
    }

    // epilogue: pair g (cols 0-63) with u (cols 64-127) via smem staging
    float* stag = (float*)smraw;
#pragma unroll
    for (int p = 0; p < 2; p++) {
        if ((wr >> 1) == p) {
            int rbase = mr - 64 * p + (lane >> 2);
            int cb = nb + (lane & 3) * 2;
#pragma unroll
            for (int mt = 0; mt < 2; mt++)
#pragma unroll
                for (int n = 0; n < 8; n++) {
                    int lr = rbase + mt * 16;
                    int c = cb + n * 8;
                    stag[lr * 132 + c]           = acc[mt][n][0];
                    stag[lr * 132 + c + 1]       = acc[mt][n][1];
                    stag[(lr + 8) * 132 + c]     = acc[mt][n][2];
                    stag[(lr + 8) * 132 + c + 1] = acc[mt][n][3];
                }
        }
        __syncthreads();
        int lr = tid >> 2, q = tid & 3;
        int grow = m0 + 64 * p + lr;
        if (grow < cnt) {
            float* dst = g_hbuf + ((size_t)e * CAP + grow) * NI + i0;
#pragma unroll
            for (int j = 0; j < 4; j++) {
                int c = q * 16 + j * 4;
                float4 g4 = *(float4*)&stag[lr * 132 + c];
                float4 u4 = *(float4*)&stag[lr * 132 + 64 + c];
                float4 o;
                o.x = g4.x / (1.f + expf(-g4.x)) * u4.x;
                o.y = g4.y / (1.f + expf(-g4.y)) * u4.y;
                o.z = g4.z / (1.f + expf(-g4.z)) * u4.z;
                o.w = g4.w / (1.f + expf(-g4.w)) * u4.w;
                *(float4*)(dst + c) = o;
            }
        }
        __syncthreads();
    }
}

// ---------------- GEMM2: y = h @ W2^T --------------------------------------
__global__ __launch_bounds__(256) void gemm2_kernel(const float* __restrict__ w2)
{
    int e = blockIdx.x, ht = blockIdx.y, mtile = blockIdx.z;
    int cnt = min(g_counts[e], CAP);
    int m0 = mtile * 128;
    if (m0 >= cnt) return;
    int h0 = ht * 128;

    extern __shared__ char smraw[];
    uint32_t sb0 = smem_u32(smraw);

    int tid = threadIdx.x, lane = tid & 31, wid = tid >> 5;
    int wr = wid & 3, wc = wid >> 2;
    int mr = wr * 32, nb = wc * 64;

    int r = tid >> 3, c4 = tid & 7;
    const float* apt[4]; const float* bpt[4];
    uint32_t soff[4];
#pragma unroll
    for (int p = 0; p < 4; p++) {
        int rp = r + 32 * p;
        int grw = m0 + rp;
        apt[p] = (grw < cnt) ? g_hbuf + ((size_t)e * CAP + grw) * NI + c4 * 4 : nullptr;
        bpt[p] = w2 + ((size_t)e * HID + h0 + rp) * NI + c4 * 4;
        soff[p] = (uint32_t)(rp * ROWB + c4 * 8);
    }

    uint32_t rowpart = (lane & 7) + ((lane >> 3) & 1) * 8;
    uint32_t colp = (lane >> 4) & 1;
    uint32_t aoff = (uint32_t)((mr + rowpart) * ROWB + colp * 16);
    uint32_t boff = (uint32_t)((nb + rowpart) * ROWB + colp * 16);

    float acc[2][8][4];
#pragma unroll
    for (int mt = 0; mt < 2; mt++)
#pragma unroll
        for (int n = 0; n < 8; n++)
#pragma unroll
            for (int q = 0; q < 4; q++) acc[mt][n][q] = 0.f;

    float4 va[4], vb[4];
#pragma unroll
    for (int p = 0; p < 4; p++) {
        va[p] = apt[p] ? __ldg((const float4*)apt[p]) : make_float4(0, 0, 0, 0);
        vb[p] = __ldg((const float4*)bpt[p]);
    }
#pragma unroll
    for (int p = 0; p < 4; p++) {
        sts_split(sb0 + soff[p],             sb0 + TILEB + soff[p],     va[p]);
        sts_split(sb0 + 2 * TILEB + soff[p], sb0 + 3 * TILEB + soff[p], vb[p]);
    }
    __syncthreads();

    const int NCH = NI / 32;
    for (int ch = 0; ch < NCH; ch++) {
        uint32_t cur = sb0 + (uint32_t)(ch & 1) * BUFB;
        bool more = (ch + 1 < NCH);
        if (more) {
            int off = (ch + 1) * 32;
#pragma unroll
            for (int p = 0; p < 4; p++) {
                va[p] = apt[p] ? __ldg((const float4*)(apt[p] + off)) : make_float4(0, 0, 0, 0);
                vb[p] = __ldg((const float4*)(bpt[p] + off));
            }
        }
        compute_chunk(cur, acc, aoff, boff);
        if (more) {
            uint32_t nxt = sb0 + (uint32_t)((ch + 1) & 1) * BUFB;
#pragma unroll
            for (int p = 0; p < 4; p++) {
                sts_split(nxt + soff[p],             nxt + TILEB + soff[p],     va[p]);
                sts_split(nxt + 2 * TILEB + soff[p], nxt + 3 * TILEB + soff[p], vb[p]);
            }
        }
        __syncthreads();
    }

    // epilogue: direct global stores
    int rb = m0 + mr + (lane >> 2);
    int cb = h0 + nb + (lane & 3) * 2;
#pragma unroll
    for (int mt = 0; mt < 2; mt++)
#pragma unroll
        for (int n = 0; n < 8; n++) {
            int rrow = rb + mt * 16;
            int c = cb + n * 8;
            if (rrow < cnt) {
                float2 v = make_float2(acc[mt][n][0], acc[mt][n][1]);
                *(float2*)(g_ybuf + ((size_t)e * CAP + rrow) * HID + c) = v;
            }
            if (rrow + 8 < cnt) {
                float2 v = make_float2(acc[mt][n][2], acc[mt][n][3]);
                *(float2*)(g_ybuf + ((size_t)e * CAP + rrow + 8) * HID + c) = v;
            }
        }
}

// ---------------- combine --------------------------------------------------
__global__ void combine_kernel(float* __restrict__ out)
{
    int t = blockIdx.x;
    __shared__ int es[TOPK];
    __shared__ float wk[TOPK];
    if (threadIdx.x < TOPK) {
        es[threadIdx.x] = g_eslot[t * TOPK + threadIdx.x];
        wk[threadIdx.x] = g_rw[t * TOPK + threadIdx.x];
    }
    __syncthreads();
    for (int h = threadIdx.x; h < HID; h += blockDim.x) {
        float acc = 0.f;
#pragma unroll
        for (int kk = 0; kk < TOPK; kk++) {
            int s = es[kk];
            if (s >= 0) acc += wk[kk] * g_ybuf[(size_t)s * HID + h];
        }
        out[(size_t)t * HID + h] = acc;
    }
}

// ---------------- launch ---------------------------------------------------
extern "C" void kernel_launch(void* const* d_in, const int* in_sizes, int n_in,
                              void* d_out, int out_size)
{
    const float* x  = (const float*)d_in[0];
    const float* gw = (const float*)d_in[1];
    const float* w1 = (const float*)d_in[2];
    const float* w2 = (const float*)d_in[3];
    const float* w3 = (const float*)d_in[4];
    float* out = (float*)d_out;
    float* logits = (out_size >= TOK * HID + TOK * NE) ? out + (size_t)TOK * HID : nullptr;

    cudaFuncSetAttribute(gemm1_kernel, cudaFuncAttributeMaxDynamicSharedMemorySize, SMEM_BYTES);
    cudaFuncSetAttribute(gemm2_kernel, cudaFuncAttributeMaxDynamicSharedMemorySize, SMEM_BYTES);

    zero_counts_kernel<<<1, 64>>>();
    router_kernel<<<TOK, 64>>>(x, gw, logits);
    dispatch_kernel<<<(TOK * TOPK + 255) / 256, 256>>>();

    dim3 g1(NE, NI / 64, CAP / 128);
    gemm1_kernel<<<g1, 256, SMEM_BYTES>>>(x, w1, w3);

    dim3 g2(NE, HID / 128, CAP / 128);
    gemm2_kernel<<<g2, 256, SMEM_BYTES>>>(w2);

    combine_kernel<<<TOK, 256>>>(out);
}

// round 8
// speedup vs baseline: 3.4249x; 1.6229x over previous
#include <cuda_runtime.h>
#include <cuda_bf16.h>
#include <cstdint>

#define TOK 512
#define HID 2048
#define NE  64
#define NI  768
#define TOPK 8
#define CAP 256

#define ROWB   80u                 // smem row stride bytes (32 bf16 + 16B pad)
#define AT_B   (64u * ROWB)        // 5120  : A tile (64 rows)
#define BT_B   (128u * ROWB)       // 10240 : B tile (128 rows)
#define O_AHI  0u
#define O_ALO  AT_B
#define O_BHI  (2u * AT_B)
#define O_BLO  (2u * AT_B + BT_B)
#define STAGE  (2u * AT_B + 2u * BT_B)   // 30720 B
#define SMEM_BYTES (2 * STAGE)           // 61440 B

// ---------------- scratch (static device allocations) ----------------------
__device__ int   g_counts[NE];
__device__ int   g_sel[TOK * TOPK];
__device__ float g_rw[TOK * TOPK];
__device__ int   g_eslot[TOK * TOPK];
__device__ int   g_toklist[NE * CAP];
__device__ float g_hbuf[(size_t)NE * CAP * NI];
__device__ float g_ybuf[(size_t)NE * CAP * HID];

// ---------------- helpers ---------------------------------------------------
__device__ __forceinline__ uint32_t smem_u32(const void* p) {
    uint32_t a;
    asm("{ .reg .u64 t; cvta.to.shared.u64 t, %1; cvt.u32.u64 %0, t; }"
        : "=r"(a) : "l"(p));
    return a;
}
__device__ __forceinline__ void ldsm4(uint32_t* r, uint32_t addr) {
    asm volatile("ldmatrix.sync.aligned.m8n8.x4.shared.b16 {%0,%1,%2,%3}, [%4];"
                 : "=r"(r[0]), "=r"(r[1]), "=r"(r[2]), "=r"(r[3]) : "r"(addr));
}
__device__ __forceinline__ void mma16816(float* d, const uint32_t* a,
                                         uint32_t b0, uint32_t b1) {
    asm volatile(
        "mma.sync.aligned.m16n8k16.row.col.f32.bf16.bf16.f32 "
        "{%0,%1,%2,%3}, {%4,%5,%6,%7}, {%8,%9}, {%0,%1,%2,%3};"
        : "+f"(d[0]), "+f"(d[1]), "+f"(d[2]), "+f"(d[3])
        : "r"(a[0]), "r"(a[1]), "r"(a[2]), "r"(a[3]), "r"(b0), "r"(b1));
}
__device__ __forceinline__ void sts_split(uint32_t hi_a, uint32_t lo_a, float4 v) {
    __nv_bfloat16 hx = __float2bfloat16(v.x), hy = __float2bfloat16(v.y),
                  hz = __float2bfloat16(v.z), hw = __float2bfloat16(v.w);
    float lx = v.x - __bfloat162float(hx), ly = v.y - __bfloat162float(hy),
          lz = v.z - __bfloat162float(hz), lw = v.w - __bfloat162float(hw);
    uint32_t h01 = (uint32_t)__bfloat16_as_ushort(hx) | ((uint32_t)__bfloat16_as_ushort(hy) << 16);
    uint32_t h23 = (uint32_t)__bfloat16_as_ushort(hz) | ((uint32_t)__bfloat16_as_ushort(hw) << 16);
    __nv_bfloat16 kx = __float2bfloat16(lx), ky = __float2bfloat16(ly),
                  kz = __float2bfloat16(lz), kw = __float2bfloat16(lw);
    uint32_t l01 = (uint32_t)__bfloat16_as_ushort(kx) | ((uint32_t)__bfloat16_as_ushort(ky) << 16);
    uint32_t l23 = (uint32_t)__bfloat16_as_ushort(kz) | ((uint32_t)__bfloat16_as_ushort(kw) << 16);
    asm volatile("st.shared.v2.b32 [%0], {%1,%2};" :: "r"(hi_a), "r"(h01), "r"(h23) : "memory");
    asm volatile("st.shared.v2.b32 [%0], {%1,%2};" :: "r"(lo_a), "r"(l01), "r"(l23) : "memory");
}

// one K=32 chunk, warp tile 32x32, term-ordered for acc-chain ILP
__device__ __forceinline__ void compute_chunk(uint32_t sb, float acc[2][4][4],
                                              uint32_t aoff, uint32_t boff) {
#pragma unroll
    for (int ks = 0; ks < 2; ks++) {
        uint32_t ah[2][4], al[2][4];
#pragma unroll
        for (int mt = 0; mt < 2; mt++) {
            uint32_t ao = aoff + mt * (16 * ROWB) + ks * 32;
            ldsm4(ah[mt], sb + O_AHI + ao);
            ldsm4(al[mt], sb + O_ALO + ao);
        }
#pragma unroll
        for (int ng = 0; ng < 2; ng++) {
            uint32_t bo = boff + ng * (16 * ROWB) + ks * 32;
            uint32_t bh[4], bl[4];
            ldsm4(bh, sb + O_BHI + bo);
            ldsm4(bl, sb + O_BLO + bo);
#pragma unroll
            for (int mt = 0; mt < 2; mt++)
#pragma unroll
                for (int t = 0; t < 2; t++)
                    mma16816(acc[mt][ng * 2 + t], ah[mt], bh[t], bh[2 + t]);
#pragma unroll
            for (int mt = 0; mt < 2; mt++)
#pragma unroll
                for (int t = 0; t < 2; t++)
                    mma16816(acc[mt][ng * 2 + t], ah[mt], bl[t], bl[2 + t]);
#pragma unroll
            for (int mt = 0; mt < 2; mt++)
#pragma unroll
                for (int t = 0; t < 2; t++)
                    mma16816(acc[mt][ng * 2 + t], al[mt], bh[t], bh[2 + t]);
        }
    }
}

// ---------------- router (fp32 exact: feeds top-k) -------------------------
__global__ void router_kernel(const float* __restrict__ x,
                              const float* __restrict__ gw,
                              float* __restrict__ logits_out)
{
    int t = blockIdx.x;
    int e = threadIdx.x;
    __shared__ float sl[NE];
    const float4* xr = (const float4*)(x + (size_t)t * HID);
    const float4* gr = (const float4*)(gw + (size_t)e * HID);
    float acc = 0.f;
#pragma unroll 4
    for (int k = 0; k < HID / 4; k++) {
        float4 a = xr[k], b = gr[k];
        acc += a.x * b.x + a.y * b.y + a.z * b.z + a.w * b.w;
    }
    sl[e] = acc;
    if (logits_out) logits_out[t * NE + e] = acc;
    __syncthreads();
    if (e == 0) {
        float tmp[NE];
        for (int i = 0; i < NE; i++) tmp[i] = sl[i];
        int sid[TOPK]; float lv[TOPK];
        for (int kk = 0; kk < TOPK; kk++) {
            int bi = 0; float bv = -3.4e38f;
            for (int i = 0; i < NE; i++)
                if (tmp[i] > bv) { bv = tmp[i]; bi = i; }
            sid[kk] = bi; lv[kk] = bv; tmp[bi] = -3.4e38f;
        }
        float m = lv[0], w[TOPK], s = 0.f;
        for (int kk = 0; kk < TOPK; kk++) { w[kk] = expf(lv[kk] - m); s += w[kk]; }
        float inv = 1.f / s;
        for (int kk = 0; kk < TOPK; kk++) {
            g_sel[t * TOPK + kk] = sid[kk];
            g_rw[t * TOPK + kk] = w[kk] * inv;
        }
    }
}

__global__ void zero_counts_kernel() { if (threadIdx.x < NE) g_counts[threadIdx.x] = 0; }

__global__ void dispatch_kernel()
{
    int a = blockIdx.x * blockDim.x + threadIdx.x;
    if (a >= TOK * TOPK) return;
    int e = g_sel[a];
    int s = atomicAdd(&g_counts[e], 1);
    if (s < CAP) { g_toklist[e * CAP + s] = a >> 3; g_eslot[a] = e * CAP + s; }
    else g_eslot[a] = -1;
}

// ---------------- GEMM1: 64 tok x (64 g | 64 u), fused SwiGLU ---------------
__global__ __launch_bounds__(256, 2) void gemm1_kernel(const float* __restrict__ x,
                                                       const float* __restrict__ w1,
                                                       const float* __restrict__ w3)
{
    int e = blockIdx.x, it = blockIdx.y, mtile = blockIdx.z;
    int cnt = min(g_counts[e], CAP);
    int m0 = mtile * 64;
    if (m0 >= cnt) return;
    int i0 = it * 64;

    extern __shared__ char smraw[];
    uint32_t sb0 = smem_u32(smraw);

    int tid = threadIdx.x, lane = tid & 31, wid = tid >> 5;
    int mr = (wid & 1) * 32, nc = (wid >> 1) * 32;

    int r = tid >> 3, c4 = tid & 7;
    // A: 2 fill rows; B: 4 fill rows
    const float* apt[2];
    const float* bpt[4];
    uint32_t sA[2], sB[4];
#pragma unroll
    for (int p = 0; p < 2; p++) {
        int rp = r + 32 * p;
        int grw = m0 + rp;
        apt[p] = (grw < cnt) ? x + (size_t)g_toklist[e * CAP + grw] * HID + c4 * 4 : nullptr;
        sA[p] = (uint32_t)(rp * ROWB + c4 * 8);
    }
#pragma unroll
    for (int p = 0; p < 4; p++) {
        int rp = r + 32 * p;
        bpt[p] = (p < 2) ? w1 + ((size_t)e * NI + i0 + rp) * HID + c4 * 4
                         : w3 + ((size_t)e * NI + i0 + rp - 64) * HID + c4 * 4;
        sB[p] = (uint32_t)(rp * ROWB + c4 * 8);
    }

    uint32_t rowpart = (lane & 7) + ((lane >> 3) & 1) * 8;
    uint32_t colp = (lane >> 4) & 1;
    uint32_t aoff = (uint32_t)((mr + rowpart) * ROWB + colp * 16);
    uint32_t boff = (uint32_t)((nc + rowpart) * ROWB + colp * 16);

    float acc[2][4][4];
#pragma unroll
    for (int mt = 0; mt < 2; mt++)
#pragma unroll
        for (int n = 0; n < 4; n++)
#pragma unroll
            for (int q = 0; q < 4; q++) acc[mt][n][q] = 0.f;

    float4 va[2], vb[4];
#pragma unroll
    for (int p = 0; p < 2; p++) va[p] = apt[p] ? __ldg((const float4*)apt[p]) : make_float4(0,0,0,0);
#pragma unroll
    for (int p = 0; p < 4; p++) vb[p] = __ldg((const float4*)bpt[p]);
#pragma unroll
    for (int p = 0; p < 2; p++) sts_split(sb0 + O_AHI + sA[p], sb0 + O_ALO + sA[p], va[p]);
#pragma unroll
    for (int p = 0; p < 4; p++) sts_split(sb0 + O_BHI + sB[p], sb0 + O_BLO + sB[p], vb[p]);
    __syncthreads();

    const int NCH = HID / 32;
    for (int ch = 0; ch < NCH; ch++) {
        uint32_t cur = sb0 + (uint32_t)(ch & 1) * STAGE;
        bool more = (ch + 1 < NCH);
        if (more) {
            int off = (ch + 1) * 32;
#pragma unroll
            for (int p = 0; p < 2; p++)
                va[p] = apt[p] ? __ldg((const float4*)(apt[p] + off)) : make_float4(0,0,0,0);
#pragma unroll
            for (int p = 0; p < 4; p++) vb[p] = __ldg((const float4*)(bpt[p] + off));
        }
        compute_chunk(cur, acc, aoff, boff);
        if (more) {
            uint32_t nxt = sb0 + (uint32_t)((ch + 1) & 1) * STAGE;
#pragma unroll
            for (int p = 0; p < 2; p++) sts_split(nxt + O_AHI + sA[p], nxt + O_ALO + sA[p], va[p]);
#pragma unroll
            for (int p = 0; p < 4; p++) sts_split(nxt + O_BHI + sB[p], nxt + O_BLO + sB[p], vb[p]);
        }
        __syncthreads();
    }

    // epilogue: stage 64x128 fp32 (stride 132), pair g/u, fused SwiGLU
    float* stag = (float*)smraw;
    {
        int rbase = mr + (lane >> 2);
        int cb = nc + (lane & 3) * 2;
#pragma unroll
        for (int mt = 0; mt < 2; mt++)
#pragma unroll
            for (int n = 0; n < 4; n++) {
                int lr = rbase + mt * 16;
                int c = cb + n * 8;
                stag[lr * 132 + c]           = acc[mt][n][0];
                stag[lr * 132 + c + 1]       = acc[mt][n][1];
                stag[(lr + 8) * 132 + c]     = acc[mt][n][2];
                stag[(lr + 8) * 132 + c + 1] = acc[mt][n][3];
            }
    }
    __syncthreads();
    {
        int lr = tid >> 2, q = tid & 3;
        int grow = m0 + lr;
        if (grow < cnt) {
            float* dst = g_hbuf + ((size_t)e * CAP + grow) * NI + i0;
#pragma unroll
            for (int j = 0; j < 4; j++) {
                int c = q * 16 + j * 4;
                float4 g4 = *(float4*)&stag[lr * 132 + c];
                float4 u4 = *(float4*)&stag[lr * 132 + 64 + c];
                float4 o;
                o.x = g4.x / (1.f + expf(-g4.x)) * u4.x;
                o.y = g4.y / (1.f + expf(-g4.y)) * u4.y;
                o.z = g4.z / (1.f + expf(-g4.z)) * u4.z;
                o.w = g4.w / (1.f + expf(-g4.w)) * u4.w;
                *(float4*)(dst + c) = o;
            }
        }
    }
}

// ---------------- GEMM2: 64 tok x 128 h-cols --------------------------------
__global__ __launch_bounds__(256, 2) void gemm2_kernel(const float* __restrict__ w2)
{
    int e = blockIdx.x, ht = blockIdx.y, mtile = blockIdx.z;
    int cnt = min(g_counts[e], CAP);
    int m0 = mtile * 64;
    if (m0 >= cnt) return;
    int h0 = ht * 128;

    extern __shared__ char smraw[];
    uint32_t sb0 = smem_u32(smraw);

    int tid = threadIdx.x, lane = tid & 31, wid = tid >> 5;
    int mr = (wid & 1) * 32, nc = (wid >> 1) * 32;

    int r = tid >> 3, c4 = tid & 7;
    const float* apt[2];
    const float* bpt[4];
    uint32_t sA[2], sB[4];
#pragma unroll
    for (int p = 0; p < 2; p++) {
        int rp = r + 32 * p;
        int grw = m0 + rp;
        apt[p] = (grw < cnt) ? g_hbuf + ((size_t)e * CAP + grw) * NI + c4 * 4 : nullptr;
        sA[p] = (uint32_t)(rp * ROWB + c4 * 8);
    }
#pragma unroll
    for (int p = 0; p < 4; p++) {
        int rp = r + 32 * p;
        bpt[p] = w2 + ((size_t)e * HID + h0 + rp) * NI + c4 * 4;
        sB[p] = (uint32_t)(rp * ROWB + c4 * 8);
    }

    uint32_t rowpart = (lane & 7) + ((lane >> 3) & 1) * 8;
    uint32_t colp = (lane >> 4) & 1;
    uint32_t aoff = (uint32_t)((mr + rowpart) * ROWB + colp * 16);
    uint32_t boff = (uint32_t)((nc + rowpart) * ROWB + colp * 16);

    float acc[2][4][4];
#pragma unroll
    for (int mt = 0; mt < 2; mt++)
#pragma unroll
        for (int n = 0; n < 4; n++)
#pragma unroll
            for (int q = 0; q < 4; q++) acc[mt][n][q] = 0.f;

    float4 va[2], vb[4];
#pragma unroll
    for (int p = 0; p < 2; p++) va[p] = apt[p] ? __ldg((const float4*)apt[p]) : make_float4(0,0,0,0);
#pragma unroll
    for (int p = 0; p < 4; p++) vb[p] = __ldg((const float4*)bpt[p]);
#pragma unroll
    for (int p = 0; p < 2; p++) sts_split(sb0 + O_AHI + sA[p], sb0 + O_ALO + sA[p], va[p]);
#pragma unroll
    for (int p = 0; p < 4; p++) sts_split(sb0 + O_BHI + sB[p], sb0 + O_BLO + sB[p], vb[p]);
    __syncthreads();

    const int NCH = NI / 32;
    for (int ch = 0; ch < NCH; ch++) {
        uint32_t cur = sb0 + (uint32_t)(ch & 1) * STAGE;
        bool more = (ch + 1 < NCH);
        if (more) {
            int off = (ch + 1) * 32;
#pragma unroll
            for (int p = 0; p < 2; p++)
                va[p] = apt[p] ? __ldg((const float4*)(apt[p] + off)) : make_float4(0,0,0,0);
#pragma unroll
            for (int p = 0; p < 4; p++) vb[p] = __ldg((const float4*)(bpt[p] + off));
        }
        compute_chunk(cur, acc, aoff, boff);
        if (more) {
            uint32_t nxt = sb0 + (uint32_t)((ch + 1) & 1) * STAGE;
#pragma unroll
            for (int p = 0; p < 2; p++) sts_split(nxt + O_AHI + sA[p], nxt + O_ALO + sA[p], va[p]);
#pragma unroll
            for (int p = 0; p < 4; p++) sts_split(nxt + O_BHI + sB[p], nxt + O_BLO + sB[p], vb[p]);
        }
        __syncthreads();
    }

    int rb = m0 + mr + (lane >> 2);
    int cb = h0 + nc + (lane & 3) * 2;
#pragma unroll
    for (int mt = 0; mt < 2; mt++)
#pragma unroll
        for (int n = 0; n < 4; n++) {
            int rrow = rb + mt * 16;
            int c = cb + n * 8;
            if (rrow < cnt)
                *(float2*)(g_ybuf + ((size_t)e * CAP + rrow) * HID + c)
                    = make_float2(acc[mt][n][0], acc[mt][n][1]);
            if (rrow + 8 < cnt)
                *(float2*)(g_ybuf + ((size_t)e * CAP + rrow + 8) * HID + c)
                    = make_float2(acc[mt][n][2], acc[mt][n][3]);
        }
}

// ---------------- combine --------------------------------------------------
__global__ void combine_kernel(float* __restrict__ out)
{
    int t = blockIdx.x;
    __shared__ int es[TOPK];
    __shared__ float wk[TOPK];
    if (threadIdx.x < TOPK) {
        es[threadIdx.x] = g_eslot[t * TOPK + threadIdx.x];
        wk[threadIdx.x] = g_rw[t * TOPK + threadIdx.x];
    }
    __syncthreads();
    for (int h = threadIdx.x; h < HID; h += blockDim.x) {
        float acc = 0.f;
#pragma unroll
        for (int kk = 0; kk < TOPK; kk++) {
            int s = es[kk];
            if (s >= 0) acc += wk[kk] * g_ybuf[(size_t)s * HID + h];
        }
        out[(size_t)t * HID + h] = acc;
    }
}

// ---------------- launch ---------------------------------------------------
extern "C" void kernel_launch(void* const* d_in, const int* in_sizes, int n_in,
                              void* d_out, int out_size)
{
    const float* x  = (const float*)d_in[0];
    const float* gw = (const float*)d_in[1];
    const float* w1 = (const float*)d_in[2];
    const float* w2 = (const float*)d_in[3];
    const float* w3 = (const float*)d_in[4];
    float* out = (float*)d_out;
    float* logits = (out_size >= TOK * HID + TOK * NE) ? out + (size_t)TOK * HID : nullptr;

    cudaFuncSetAttribute(gemm1_kernel, cudaFuncAttributeMaxDynamicSharedMemorySize, SMEM_BYTES);
    cudaFuncSetAttribute(gemm2_kernel, cudaFuncAttributeMaxDynamicSharedMemorySize, SMEM_BYTES);

    zero_counts_kernel<<<1, 64>>>();
    router_kernel<<<TOK, 64>>>(x, gw, logits);
    dispatch_kernel<<<(TOK * TOPK + 255) / 256, 256>>>();

    dim3 g1(NE, NI / 64, CAP / 64);
    gemm1_kernel<<<g1, 256, SMEM_BYTES>>>(x, w1, w3);

    dim3 g2(NE, HID / 128, CAP / 64);
    gemm2_kernel<<<g2, 256, SMEM_BYTES>>>(w2);

    combine_kernel<<<TOK, 256>>>(out);
}

// round 9
// speedup vs baseline: 3.4960x; 1.0208x over previous
#include <cuda_runtime.h>
#include <cuda_bf16.h>
#include <cstdint>

#define TOK 512
#define HID 2048
#define NE  64
#define NI  768
#define TOPK 8
#define CAP 256

#define ROWB   80u                 // smem row stride bytes (32 bf16 + 16B pad)
#define AT_B   (64u * ROWB)        // 5120  : A tile (64 rows)
#define BT_B   (128u * ROWB)       // 10240 : B tile (128 rows)
#define O_AHI  0u
#define O_ALO  AT_B
#define O_BHI  (2u * AT_B)
#define O_BLO  (2u * AT_B + BT_B)
#define STAGE  (2u * AT_B + 2u * BT_B)   // 30720 B
#define SMEM_BYTES (2 * STAGE)           // 61440 B

// ---------------- scratch (static device allocations) ----------------------
__device__ int   g_counts[NE];
__device__ int   g_sel[TOK * TOPK];
__device__ float g_rw[TOK * TOPK];
__device__ int   g_toklist[NE * CAP];
__device__ float g_slotw[NE * CAP];
__device__ float g_hbuf[(size_t)NE * CAP * NI];

// ---------------- helpers ---------------------------------------------------
__device__ __forceinline__ uint32_t smem_u32(const void* p) {
    uint32_t a;
    asm("{ .reg .u64 t; cvta.to.shared.u64 t, %1; cvt.u32.u64 %0, t; }"
        : "=r"(a) : "l"(p));
    return a;
}
__device__ __forceinline__ void ldsm4(uint32_t* r, uint32_t addr) {
    asm volatile("ldmatrix.sync.aligned.m8n8.x4.shared.b16 {%0,%1,%2,%3}, [%4];"
                 : "=r"(r[0]), "=r"(r[1]), "=r"(r[2]), "=r"(r[3]) : "r"(addr));
}
__device__ __forceinline__ void mma16816(float* d, const uint32_t* a,
                                         uint32_t b0, uint32_t b1) {
    asm volatile(
        "mma.sync.aligned.m16n8k16.row.col.f32.bf16.bf16.f32 "
        "{%0,%1,%2,%3}, {%4,%5,%6,%7}, {%8,%9}, {%0,%1,%2,%3};"
        : "+f"(d[0]), "+f"(d[1]), "+f"(d[2]), "+f"(d[3])
        : "r"(a[0]), "r"(a[1]), "r"(a[2]), "r"(a[3]), "r"(b0), "r"(b1));
}
__device__ __forceinline__ void sts_split(uint32_t hi_a, uint32_t lo_a, float4 v) {
    __nv_bfloat16 hx = __float2bfloat16(v.x), hy = __float2bfloat16(v.y),
                  hz = __float2bfloat16(v.z), hw = __float2bfloat16(v.w);
    float lx = v.x - __bfloat162float(hx), ly = v.y - __bfloat162float(hy),
          lz = v.z - __bfloat162float(hz), lw = v.w - __bfloat162float(hw);
    uint32_t h01 = (uint32_t)__bfloat16_as_ushort(hx) | ((uint32_t)__bfloat16_as_ushort(hy) << 16);
    uint32_t h23 = (uint32_t)__bfloat16_as_ushort(hz) | ((uint32_t)__bfloat16_as_ushort(hw) << 16);
    __nv_bfloat16 kx = __float2bfloat16(lx), ky = __float2bfloat16(ly),
                  kz = __float2bfloat16(lz), kw = __float2bfloat16(lw);
    uint32_t l01 = (uint32_t)__bfloat16_as_ushort(kx) | ((uint32_t)__bfloat16_as_ushort(ky) << 16);
    uint32_t l23 = (uint32_t)__bfloat16_as_ushort(kz) | ((uint32_t)__bfloat16_as_ushort(kw) << 16);
    asm volatile("st.shared.v2.b32 [%0], {%1,%2};" :: "r"(hi_a), "r"(h01), "r"(h23) : "memory");
    asm volatile("st.shared.v2.b32 [%0], {%1,%2};" :: "r"(lo_a), "r"(l01), "r"(l23) : "memory");
}

// one K=32 chunk, warp tile 32x32; mmask bit per 16-row m-slice (warp-uniform)
__device__ __forceinline__ void compute_chunk(uint32_t sb, float acc[2][4][4],
                                              uint32_t aoff, uint32_t boff,
                                              int mmask) {
    if (!mmask) return;
#pragma unroll
    for (int ks = 0; ks < 2; ks++) {
        uint32_t ah[2][4], al[2][4];
#pragma unroll
        for (int mt = 0; mt < 2; mt++) {
            if (!(mmask & (1 << mt))) continue;
            uint32_t ao = aoff + mt * (16 * ROWB) + ks * 32;
            ldsm4(ah[mt], sb + O_AHI + ao);
            ldsm4(al[mt], sb + O_ALO + ao);
        }
#pragma unroll
        for (int ng = 0; ng < 2; ng++) {
            uint32_t bo = boff + ng * (16 * ROWB) + ks * 32;
            uint32_t bh[4], bl[4];
            ldsm4(bh, sb + O_BHI + bo);
            ldsm4(bl, sb + O_BLO + bo);
#pragma unroll
            for (int mt = 0; mt < 2; mt++)
                if (mmask & (1 << mt))
#pragma unroll
                    for (int t = 0; t < 2; t++)
                        mma16816(acc[mt][ng * 2 + t], ah[mt], bh[t], bh[2 + t]);
#pragma unroll
            for (int mt = 0; mt < 2; mt++)
                if (mmask & (1 << mt))
#pragma unroll
                    for (int t = 0; t < 2; t++)
                        mma16816(acc[mt][ng * 2 + t], ah[mt], bl[t], bl[2 + t]);
#pragma unroll
            for (int mt = 0; mt < 2; mt++)
                if (mmask & (1 << mt))
#pragma unroll
                    for (int t = 0; t < 2; t++)
                        mma16816(acc[mt][ng * 2 + t], al[mt], bh[t], bh[2 + t]);
        }
    }
}

// ---------------- router (fp32 exact: feeds top-k) -------------------------
__global__ void router_kernel(const float* __restrict__ x,
                              const float* __restrict__ gw,
                              float* __restrict__ logits_out)
{
    int t = blockIdx.x;
    int e = threadIdx.x;
    __shared__ float sl[NE];
    const float4* xr = (const float4*)(x + (size_t)t * HID);
    const float4* gr = (const float4*)(gw + (size_t)e * HID);
    float acc = 0.f;
#pragma unroll 4
    for (int k = 0; k < HID / 4; k++) {
        float4 a = xr[k], b = gr[k];
        acc += a.x * b.x + a.y * b.y + a.z * b.z + a.w * b.w;
    }
    sl[e] = acc;
    if (logits_out) logits_out[t * NE + e] = acc;
    __syncthreads();
    if (e == 0) {
        float tmp[NE];
        for (int i = 0; i < NE; i++) tmp[i] = sl[i];
        int sid[TOPK]; float lv[TOPK];
        for (int kk = 0; kk < TOPK; kk++) {
            int bi = 0; float bv = -3.4e38f;
            for (int i = 0; i < NE; i++)
                if (tmp[i] > bv) { bv = tmp[i]; bi = i; }
            sid[kk] = bi; lv[kk] = bv; tmp[bi] = -3.4e38f;
        }
        float m = lv[0], w[TOPK], s = 0.f;
        for (int kk = 0; kk < TOPK; kk++) { w[kk] = expf(lv[kk] - m); s += w[kk]; }
        float inv = 1.f / s;
        for (int kk = 0; kk < TOPK; kk++) {
            g_sel[t * TOPK + kk] = sid[kk];
            g_rw[t * TOPK + kk] = w[kk] * inv;
        }
    }
}

__global__ void zero_counts_kernel() { if (threadIdx.x < NE) g_counts[threadIdx.x] = 0; }

__global__ void dispatch_kernel()
{
    int a = blockIdx.x * blockDim.x + threadIdx.x;
    if (a >= TOK * TOPK) return;
    int e = g_sel[a];
    int s = atomicAdd(&g_counts[e], 1);
    if (s < CAP) {
        g_toklist[e * CAP + s] = a >> 3;
        g_slotw[e * CAP + s] = g_rw[a];
    }
}

__global__ void zero_out_kernel(float* __restrict__ out)
{
    int i = blockIdx.x * blockDim.x + threadIdx.x;
    if (i < TOK * HID / 4) ((float4*)out)[i] = make_float4(0, 0, 0, 0);
}

// ---------------- GEMM1: 64 tok x (64 g | 64 u), fused SwiGLU ---------------
__global__ __launch_bounds__(256, 2) void gemm1_kernel(const float* __restrict__ x,
                                                       const float* __restrict__ w1,
                                                       const float* __restrict__ w3)
{
    int e = blockIdx.x, it = blockIdx.y, mtile = blockIdx.z;
    int cnt = min(g_counts[e], CAP);
    int m0 = mtile * 64;
    if (m0 >= cnt) return;
    int i0 = it * 64;

    extern __shared__ char smraw[];
    uint32_t sb0 = smem_u32(smraw);

    int tid = threadIdx.x, lane = tid & 31, wid = tid >> 5;
    int mr = (wid & 1) * 32, nc = (wid >> 1) * 32;
    int mmask = ((m0 + mr < cnt) ? 1 : 0) | ((m0 + mr + 16 < cnt) ? 2 : 0);

    int r = tid >> 3, c4 = tid & 7;
    const float* apt[2];
    const float* bpt[4];
    uint32_t sA[2], sB[4];
    bool aval[2];
#pragma unroll
    for (int p = 0; p < 2; p++) {
        int rp = r + 32 * p;
        int grw = m0 + rp;
        aval[p] = (m0 + (rp & ~15)) < cnt;      // 16-row slice has a consumer
        apt[p] = (grw < cnt) ? x + (size_t)g_toklist[e * CAP + grw] * HID + c4 * 4 : nullptr;
        sA[p] = (uint32_t)(rp * ROWB + c4 * 8);
    }
#pragma unroll
    for (int p = 0; p < 4; p++) {
        int rp = r + 32 * p;
        bpt[p] = (p < 2) ? w1 + ((size_t)e * NI + i0 + rp) * HID + c4 * 4
                         : w3 + ((size_t)e * NI + i0 + rp - 64) * HID + c4 * 4;
        sB[p] = (uint32_t)(rp * ROWB + c4 * 8);
    }

    uint32_t rowpart = (lane & 7) + ((lane >> 3) & 1) * 8;
    uint32_t colp = (lane >> 4) & 1;
    uint32_t aoff = (uint32_t)((mr + rowpart) * ROWB + colp * 16);
    uint32_t boff = (uint32_t)((nc + rowpart) * ROWB + colp * 16);

    float acc[2][4][4];
#pragma unroll
    for (int mt = 0; mt < 2; mt++)
#pragma unroll
        for (int n = 0; n < 4; n++)
#pragma unroll
            for (int q = 0; q < 4; q++) acc[mt][n][q] = 0.f;

    float4 va[2], vb[4];
#pragma unroll
    for (int p = 0; p < 2; p++) va[p] = apt[p] ? __ldg((const float4*)apt[p]) : make_float4(0,0,0,0);
#pragma unroll
    for (int p = 0; p < 4; p++) vb[p] = __ldg((const float4*)bpt[p]);
#pragma unroll
    for (int p = 0; p < 2; p++)
        if (aval[p]) sts_split(sb0 + O_AHI + sA[p], sb0 + O_ALO + sA[p], va[p]);
#pragma unroll
    for (int p = 0; p < 4; p++) sts_split(sb0 + O_BHI + sB[p], sb0 + O_BLO + sB[p], vb[p]);
    __syncthreads();

    const int NCH = HID / 32;
    for (int ch = 0; ch < NCH; ch++) {
        uint32_t cur = sb0 + (uint32_t)(ch & 1) * STAGE;
        bool more = (ch + 1 < NCH);
        if (more) {
            int off = (ch + 1) * 32;
#pragma unroll
            for (int p = 0; p < 2; p++)
                va[p] = apt[p] ? __ldg((const float4*)(apt[p] + off)) : make_float4(0,0,0,0);
#pragma unroll
            for (int p = 0; p < 4; p++) vb[p] = __ldg((const float4*)(bpt[p] + off));
        }
        compute_chunk(cur, acc, aoff, boff, mmask);
        if (more) {
            uint32_t nxt = sb0 + (uint32_t)((ch + 1) & 1) * STAGE;
#pragma unroll
            for (int p = 0; p < 2; p++)
                if (aval[p]) sts_split(nxt + O_AHI + sA[p], nxt + O_ALO + sA[p], va[p]);
#pragma unroll
            for (int p = 0; p < 4; p++) sts_split(nxt + O_BHI + sB[p], nxt + O_BLO + sB[p], vb[p]);
        }
        __syncthreads();
    }

    // epilogue: stage 64x128 fp32 (stride 132), pair g/u, fused SwiGLU
    float* stag = (float*)smraw;
    {
        int rbase = mr + (lane >> 2);
        int cb = nc + (lane & 3) * 2;
#pragma unroll
        for (int mt = 0; mt < 2; mt++)
#pragma unroll
            for (int n = 0; n < 4; n++) {
                int lr = rbase + mt * 16;
                int c = cb + n * 8;
                stag[lr * 132 + c]           = acc[mt][n][0];
                stag[lr * 132 + c + 1]       = acc[mt][n][1];
                stag[(lr + 8) * 132 + c]     = acc[mt][n][2];
                stag[(lr + 8) * 132 + c + 1] = acc[mt][n][3];
            }
    }
    __syncthreads();
    {
        int lr = tid >> 2, q = tid & 3;
        int grow = m0 + lr;
        if (grow < cnt) {
            float* dst = g_hbuf + ((size_t)e * CAP + grow) * NI + i0;
#pragma unroll
            for (int j = 0; j < 4; j++) {
                int c = q * 16 + j * 4;
                float4 g4 = *(float4*)&stag[lr * 132 + c];
                float4 u4 = *(float4*)&stag[lr * 132 + 64 + c];
                float4 o;
                o.x = g4.x / (1.f + expf(-g4.x)) * u4.x;
                o.y = g4.y / (1.f + expf(-g4.y)) * u4.y;
                o.z = g4.z / (1.f + expf(-g4.z)) * u4.z;
                o.w = g4.w / (1.f + expf(-g4.w)) * u4.w;
                *(float4*)(dst + c) = o;
            }
        }
    }
}

// ---------------- GEMM2: 64 tok x 128 h-cols, fused weighted combine --------
__global__ __launch_bounds__(256, 2) void gemm2_kernel(const float* __restrict__ w2,
                                                       float* __restrict__ out)
{
    int e = blockIdx.x, ht = blockIdx.y, mtile = blockIdx.z;
    int cnt = min(g_counts[e], CAP);
    int m0 = mtile * 64;
    if (m0 >= cnt) return;
    int h0 = ht * 128;

    extern __shared__ char smraw[];
    uint32_t sb0 = smem_u32(smraw);

    int tid = threadIdx.x, lane = tid & 31, wid = tid >> 5;
    int mr = (wid & 1) * 32, nc = (wid >> 1) * 32;
    int mmask = ((m0 + mr < cnt) ? 1 : 0) | ((m0 + mr + 16 < cnt) ? 2 : 0);

    int r = tid >> 3, c4 = tid & 7;
    const float* apt[2];
    const float* bpt[4];
    uint32_t sA[2], sB[4];
    bool aval[2];
#pragma unroll
    for (int p = 0; p < 2; p++) {
        int rp = r + 32 * p;
        int grw = m0 + rp;
        aval[p] = (m0 + (rp & ~15)) < cnt;
        apt[p] = (grw < cnt) ? g_hbuf + ((size_t)e * CAP + grw) * NI + c4 * 4 : nullptr;
        sA[p] = (uint32_t)(rp * ROWB + c4 * 8);
    }
#pragma unroll
    for (int p = 0; p < 4; p++) {
        int rp = r + 32 * p;
        bpt[p] = w2 + ((size_t)e * HID + h0 + rp) * NI + c4 * 4;
        sB[p] = (uint32_t)(rp * ROWB + c4 * 8);
    }

    uint32_t rowpart = (lane & 7) + ((lane >> 3) & 1) * 8;
    uint32_t colp = (lane >> 4) & 1;
    uint32_t aoff = (uint32_t)((mr + rowpart) * ROWB + colp * 16);
    uint32_t boff = (uint32_t)((nc + rowpart) * ROWB + colp * 16);

    float acc[2][4][4];
#pragma unroll
    for (int mt = 0; mt < 2; mt++)
#pragma unroll
        for (int n = 0; n < 4; n++)
#pragma unroll
            for (int q = 0; q < 4; q++) acc[mt][n][q] = 0.f;

    float4 va[2], vb[4];
#pragma unroll
    for (int p = 0; p < 2; p++) va[p] = apt[p] ? __ldg((const float4*)apt[p]) : make_float4(0,0,0,0);
#pragma unroll
    for (int p = 0; p < 4; p++) vb[p] = __ldg((const float4*)bpt[p]);
#pragma unroll
    for (int p = 0; p < 2; p++)
        if (aval[p]) sts_split(sb0 + O_AHI + sA[p], sb0 + O_ALO + sA[p], va[p]);
#pragma unroll
    for (int p = 0; p < 4; p++) sts_split(sb0 + O_BHI + sB[p], sb0 + O_BLO + sB[p], vb[p]);
    __syncthreads();

    const int NCH = NI / 32;
    for (int ch = 0; ch < NCH; ch++) {
        uint32_t cur = sb0 + (uint32_t)(ch & 1) * STAGE;
        bool more = (ch + 1 < NCH);
        if (more) {
            int off = (ch + 1) * 32;
#pragma unroll
            for (int p = 0; p < 2; p++)
                va[p] = apt[p] ? __ldg((const float4*)(apt[p] + off)) : make_float4(0,0,0,0);
#pragma unroll
            for (int p = 0; p < 4; p++) vb[p] = __ldg((const float4*)(bpt[p] + off));
        }
        compute_chunk(cur, acc, aoff, boff, mmask);
        if (more) {
            uint32_t nxt = sb0 + (uint32_t)((ch + 1) & 1) * STAGE;
#pragma unroll
            for (int p = 0; p < 2; p++)
                if (aval[p]) sts_split(nxt + O_AHI + sA[p], nxt + O_ALO + sA[p], va[p]);
#pragma unroll
            for (int p = 0; p < 4; p++) sts_split(nxt + O_BHI + sB[p], nxt + O_BLO + sB[p], vb[p]);
        }
        __syncthreads();
    }

    // fused combine: out[token] += w * y  (8 fp32 contributions per element)
    int rb = mr + (lane >> 2);
    int cb = h0 + nc + (lane & 3) * 2;
#pragma unroll
    for (int mt = 0; mt < 2; mt++)
#pragma unroll
        for (int half = 0; half < 2; half++) {
            int grow = m0 + rb + mt * 16 + half * 8;
            if (grow < cnt) {
                int tok = g_toklist[e * CAP + grow];
                float w = g_slotw[e * CAP + grow];
                float* dst = out + (size_t)tok * HID;
#pragma unroll
                for (int n = 0; n < 4; n++) {
                    int c = cb + n * 8;
                    atomicAdd(dst + c,     w * acc[mt][n][half * 2 + 0]);
                    atomicAdd(dst + c + 1, w * acc[mt][n][half * 2 + 1]);
                }
            }
        }
}

// ---------------- launch ---------------------------------------------------
extern "C" void kernel_launch(void* const* d_in, const int* in_sizes, int n_in,
                              void* d_out, int out_size)
{
    const float* x  = (const float*)d_in[0];
    const float* gw = (const float*)d_in[1];
    const float* w1 = (const float*)d_in[2];
    const float* w2 = (const float*)d_in[3];
    const float* w3 = (const float*)d_in[4];
    float* out = (float*)d_out;
    float* logits = (out_size >= TOK * HID + TOK * NE) ? out + (size_t)TOK * HID : nullptr;

    cudaFuncSetAttribute(gemm1_kernel, cudaFuncAttributeMaxDynamicSharedMemorySize, SMEM_BYTES);
    cudaFuncSetAttribute(gemm2_kernel, cudaFuncAttributeMaxDynamicSharedMemorySize, SMEM_BYTES);

    zero_counts_kernel<<<1, 64>>>();
    router_kernel<<<TOK, 64>>>(x, gw, logits);
    dispatch_kernel<<<(TOK * TOPK + 255) / 256, 256>>>();
    zero_out_kernel<<<(TOK * HID / 4 + 255) / 256, 256>>>(out);

    dim3 g1(NE, NI / 64, CAP / 64);
    gemm1_kernel<<<g1, 256, SMEM_BYTES>>>(x, w1, w3);

    dim3 g2(NE, HID / 128, CAP / 64);
    gemm2_kernel<<<g2, 256, SMEM_BYTES>>>(w2, out);
}